// round 16
// baseline (speedup 1.0000x reference)
#include <cuda_runtime.h>
#include <cuda_fp16.h>
#include <math.h>
#include <stdint.h>

#define F      128
#define NMAX   80000
#define EMAX   640000
#define SMS    132          // smem row stride (floats), conflict-free for frag loads
#define MTILE  256          // GEMM rows per block
#define GT     512          // GEMM threads per block (16 warps)

// ---------------- scratch (static device globals; no allocation) ----------------
// g_deg starts zeroed (static init); k_scan23 re-zeroes it for the next call.
__device__ __align__(16) float  g_buf0[NMAX * F];  // prop output / GEMM input (fp32)
__device__ __align__(16) __half g_h  [NMAX * F];   // hidden after conv1+relu (fp16)
__device__ __align__(16) __half g_z  [NMAX * F];   // latent z (fp16)
__device__ __align__(16) float  g_wt1 [F * F];     // W1^T,  tf32-rounded
__device__ __align__(16) float  g_wtmu[F * F];
__device__ __align__(16) float  g_wtlv[F * F];
__device__ float g_dinv[NMAX];
__device__ float g_coef[EMAX];
__device__ int   g_deg [NMAX];
__device__ int   g_rowptr[NMAX + 1];
__device__ int   g_cur [NMAX];
__device__ int   g_csr [EMAX];
__device__ int   g_bsum[1024];

// ---------------- helpers ----------------
__device__ __forceinline__ float f2tf32(float x) {
    uint32_t b;
    asm("cvt.rna.tf32.f32 %0, %1;" : "=r"(b) : "f"(x));
    return __uint_as_float(b);
}
__device__ __forceinline__ void mma_tf32(float* c, const uint32_t* a, const uint32_t* b) {
    asm volatile(
        "mma.sync.aligned.m16n8k8.row.col.f32.tf32.tf32.f32 "
        "{%0,%1,%2,%3}, {%4,%5,%6,%7}, {%8,%9}, {%0,%1,%2,%3};"
        : "+f"(c[0]), "+f"(c[1]), "+f"(c[2]), "+f"(c[3])
        : "r"(a[0]), "r"(a[1]), "r"(a[2]), "r"(a[3]), "r"(b[0]), "r"(b[1]));
}
__device__ __forceinline__ float4 h4_to_f4(const __half* p) {
    uint2 u = *(const uint2*)p;
    __half2 h0 = *reinterpret_cast<__half2*>(&u.x);
    __half2 h1 = *reinterpret_cast<__half2*>(&u.y);
    float2 f0 = __half22float2(h0), f1 = __half22float2(h1);
    return make_float4(f0.x, f0.y, f1.x, f1.y);
}

// ---------------- CSR construction ----------------
// 4 edges per thread (int4 loads) -> MLP 4 against L2 atomic latency.
__global__ void k_count(const int* __restrict__ dst, int e) {
    int i = (blockIdx.x * blockDim.x + threadIdx.x) * 4;
    if (i + 3 < e) {
        int4 d = *(const int4*)(dst + i);
        atomicAdd(&g_deg[d.x], 1);
        atomicAdd(&g_deg[d.y], 1);
        atomicAdd(&g_deg[d.z], 1);
        atomicAdd(&g_deg[d.w], 1);
    } else {
        for (; i < e; i++) atomicAdd(&g_deg[dst[i]], 1);
    }
}
__global__ void k_scan1(int n) {
    __shared__ int s[256];
    int t = threadIdx.x;
    int i = blockIdx.x * 256 + t;
    int d = (i < n) ? g_deg[i] : 0;
    if (i < n) g_dinv[i] = rsqrtf((float)(d + 1));
    s[t] = d; __syncthreads();
#pragma unroll
    for (int off = 1; off < 256; off <<= 1) {
        int v = (t >= off) ? s[t - off] : 0;
        __syncthreads();
        s[t] += v;
        __syncthreads();
    }
    if (i < n) g_rowptr[i] = s[t] - d;
    if (t == 255) g_bsum[blockIdx.x] = s[255];
}
__global__ void k_scan23(int nb, int n) {
    __shared__ int s[512];
    int t = threadIdx.x;
    int v = (t < nb) ? g_bsum[t] : 0;
    s[t] = v; __syncthreads();
#pragma unroll
    for (int off = 1; off < 512; off <<= 1) {
        int u = (t >= off) ? s[t - off] : 0;
        __syncthreads();
        s[t] += u;
        __syncthreads();
    }
    int bid = blockIdx.x;
    if (t < 256) {
        int base = (bid == 0) ? 0 : s[bid - 1];
        int i = bid * 256 + t;
        if (i < n) {
            int r = g_rowptr[i] + base;
            g_rowptr[i] = r;
            g_cur[i] = r;
            g_deg[i] = 0;                // prep for next call
        }
    }
    if (bid == 0 && t == 0) g_rowptr[n] = s[nb - 1];
}
// 4 edges per thread (int4 loads of src & dst)
__global__ void k_place(const int* __restrict__ src, const int* __restrict__ dst, int e) {
    int i = (blockIdx.x * blockDim.x + threadIdx.x) * 4;
    if (i + 3 < e) {
        int4 d = *(const int4*)(dst + i);
        int4 s = *(const int4*)(src + i);
        int p0 = atomicAdd(&g_cur[d.x], 1);
        int p1 = atomicAdd(&g_cur[d.y], 1);
        int p2 = atomicAdd(&g_cur[d.z], 1);
        int p3 = atomicAdd(&g_cur[d.w], 1);
        g_csr[p0] = s.x; g_coef[p0] = g_dinv[s.x] * g_dinv[d.x];
        g_csr[p1] = s.y; g_coef[p1] = g_dinv[s.y] * g_dinv[d.y];
        g_csr[p2] = s.z; g_coef[p2] = g_dinv[s.z] * g_dinv[d.z];
        g_csr[p3] = s.w; g_coef[p3] = g_dinv[s.w] * g_dinv[d.w];
    } else {
        for (; i < e; i++) {
            int dd = dst[i], ss = src[i];
            int slot = atomicAdd(&g_cur[dd], 1);
            g_csr[slot] = ss;
            g_coef[slot] = g_dinv[ss] * g_dinv[dd];
        }
    }
}

// ---------------- weight transpose + tf32 rounding ----------------
__global__ void k_prep_w(const float* __restrict__ W1, const float* __restrict__ Wmu,
                         const float* __restrict__ Wlv) {
    const float* src = (blockIdx.z == 0) ? W1 : (blockIdx.z == 1) ? Wmu : Wlv;
    float* dst = (blockIdx.z == 0) ? g_wt1 : (blockIdx.z == 1) ? g_wtmu : g_wtlv;
    __shared__ float t[32][33];
    int tx = threadIdx.x, ty = threadIdx.y;
    int bx = blockIdx.x * 32, by = blockIdx.y * 32;
#pragma unroll
    for (int i = 0; i < 32; i += 8)
        t[ty + i][tx] = src[(by + ty + i) * F + bx + tx];
    __syncthreads();
#pragma unroll
    for (int i = 0; i < 32; i += 8)
        dst[(bx + ty + i) * F + by + tx] = f2tf32(t[tx][ty + i]);
}

// ---------------- propagation (fp32 table): out = P t ----------------
__global__ __launch_bounds__(256) void k_prop_f32(const float* __restrict__ t,
                                                  float* __restrict__ out, int n) {
    int w = (blockIdx.x * blockDim.x + threadIdx.x) >> 5;
    if (w >= n) return;
    int lane = threadIdx.x & 31;

    const float4* t4 = (const float4*)t;
    float di = g_dinv[w];
    float4 v = t4[(size_t)w * 32 + lane];
    float cs = di * di;
    float4 acc = make_float4(v.x * cs, v.y * cs, v.z * cs, v.w * cs);

    int j = g_rowptr[w], end = g_rowptr[w + 1];
    for (; j + 3 < end; j += 4) {
        int s0 = g_csr[j], s1 = g_csr[j + 1], s2 = g_csr[j + 2], s3 = g_csr[j + 3];
        float c0 = g_coef[j], c1 = g_coef[j + 1], c2 = g_coef[j + 2], c3 = g_coef[j + 3];
        float4 u0 = t4[(size_t)s0 * 32 + lane];
        float4 u1 = t4[(size_t)s1 * 32 + lane];
        float4 u2 = t4[(size_t)s2 * 32 + lane];
        float4 u3 = t4[(size_t)s3 * 32 + lane];
        acc.x = fmaf(u0.x, c0, fmaf(u1.x, c1, fmaf(u2.x, c2, fmaf(u3.x, c3, acc.x))));
        acc.y = fmaf(u0.y, c0, fmaf(u1.y, c1, fmaf(u2.y, c2, fmaf(u3.y, c3, acc.y))));
        acc.z = fmaf(u0.z, c0, fmaf(u1.z, c1, fmaf(u2.z, c2, fmaf(u3.z, c3, acc.z))));
        acc.w = fmaf(u0.w, c0, fmaf(u1.w, c1, fmaf(u2.w, c2, fmaf(u3.w, c3, acc.w))));
    }
    for (; j < end; j++) {
        int s0 = g_csr[j];
        float c0 = g_coef[j];
        float4 u0 = t4[(size_t)s0 * 32 + lane];
        acc.x = fmaf(u0.x, c0, acc.x);
        acc.y = fmaf(u0.y, c0, acc.y);
        acc.z = fmaf(u0.z, c0, acc.z);
        acc.w = fmaf(u0.w, c0, acc.w);
    }
    ((float4*)out)[(size_t)w * 32 + lane] = acc;
}

// ---------------- propagation (fp16 table): out = P t ----------------
__global__ __launch_bounds__(256) void k_prop_f16(const __half* __restrict__ t,
                                                  float* __restrict__ out, int n) {
    int w = (blockIdx.x * blockDim.x + threadIdx.x) >> 5;
    if (w >= n) return;
    int lane = threadIdx.x & 31;
    int fo = lane * 4;

    float di = g_dinv[w];
    float4 v = h4_to_f4(t + (size_t)w * F + fo);
    float cs = di * di;
    float4 acc = make_float4(v.x * cs, v.y * cs, v.z * cs, v.w * cs);

    int j = g_rowptr[w], end = g_rowptr[w + 1];
    for (; j + 3 < end; j += 4) {
        int s0 = g_csr[j], s1 = g_csr[j + 1], s2 = g_csr[j + 2], s3 = g_csr[j + 3];
        float c0 = g_coef[j], c1 = g_coef[j + 1], c2 = g_coef[j + 2], c3 = g_coef[j + 3];
        float4 u0 = h4_to_f4(t + (size_t)s0 * F + fo);
        float4 u1 = h4_to_f4(t + (size_t)s1 * F + fo);
        float4 u2 = h4_to_f4(t + (size_t)s2 * F + fo);
        float4 u3 = h4_to_f4(t + (size_t)s3 * F + fo);
        acc.x = fmaf(u0.x, c0, fmaf(u1.x, c1, fmaf(u2.x, c2, fmaf(u3.x, c3, acc.x))));
        acc.y = fmaf(u0.y, c0, fmaf(u1.y, c1, fmaf(u2.y, c2, fmaf(u3.y, c3, acc.y))));
        acc.z = fmaf(u0.z, c0, fmaf(u1.z, c1, fmaf(u2.z, c2, fmaf(u3.z, c3, acc.z))));
        acc.w = fmaf(u0.w, c0, fmaf(u1.w, c1, fmaf(u2.w, c2, fmaf(u3.w, c3, acc.w))));
    }
    for (; j < end; j++) {
        int s0 = g_csr[j];
        float c0 = g_coef[j];
        float4 u0 = h4_to_f4(t + (size_t)s0 * F + fo);
        acc.x = fmaf(u0.x, c0, acc.x);
        acc.y = fmaf(u0.y, c0, acc.y);
        acc.z = fmaf(u0.z, c0, acc.z);
        acc.w = fmaf(u0.w, c0, acc.w);
    }
    ((float4*)out)[(size_t)w * 32 + lane] = acc;
}

// ---------------- TF32 mma.sync GEMM: C = A @ Bt^T + bias, + epilogue ----------
// 256-row block tile, 16 warps (512 thr), 64x32 warp tiles -> 4 warps/SMSP.
// A and first-B staging interleaved (both load streams in flight, one sync).
// mode 1: H0 = half(relu(...))     mode 2: C0 = sigmoid(...)
// mode 3: C0 = mu, C1 = logvar, H0 = half(eps*exp(0.5*lv)+mu)
__global__ __launch_bounds__(GT, 1) void k_gemm_mma(
    const float* __restrict__ A,
    const float* __restrict__ Bt0, const float* __restrict__ Bt1,
    const float* __restrict__ bias0, const float* __restrict__ bias1,
    const float* __restrict__ eps,
    float* __restrict__ C0, float* __restrict__ C1, __half* __restrict__ H0,
    int n, int mode)
{
    extern __shared__ float smf[];
    float* As = smf;                    // MTILE x SMS
    float* Bs = As + MTILE * SMS;       // 128 x SMS

    const int tid  = threadIdx.x;
    const int warp = tid >> 5, lane = tid & 31;
    const int row0 = blockIdx.x * MTILE;
    const int nbt  = (mode == 3) ? 2 : 1;

    // stage B tile 0 (interleave with A staging; B is small: 8 float4/thread)
    for (int q = tid; q < 4096; q += GT) {
        int r = q >> 5, c = q & 31;
        float4 v = *(const float4*)(Bt0 + (size_t)r * F + c * 4);
        *(float4*)(Bs + r * SMS + c * 4) = v;
    }
    // stage A (tf32-round on the fly)
    for (int t = tid; t < MTILE * 32; t += GT) {
        int r = t >> 5, q = t & 31;
        int gr = row0 + r; if (gr >= n) gr = n - 1;
        float4 v = *(const float4*)(A + (size_t)gr * F + q * 4);
        v.x = f2tf32(v.x); v.y = f2tf32(v.y); v.z = f2tf32(v.z); v.w = f2tf32(v.w);
        *(float4*)(As + r * SMS + q * 4) = v;
    }
    __syncthreads();

    const int wm = warp >> 2;    // 0..3  (64-row bands)
    const int wn = warp & 3;     // 0..3  (32-col bands)
    const int gid = lane >> 2, tig = lane & 3;
    const float* Aw = As + (wm * 64) * SMS;

    for (int bt = 0; bt < nbt; bt++) {
        if (bt == 1) {
            __syncthreads();
            for (int q = tid; q < 4096; q += GT) {
                int r = q >> 5, c = q & 31;
                float4 v = *(const float4*)(Bt1 + (size_t)r * F + c * 4);
                *(float4*)(Bs + r * SMS + c * 4) = v;
            }
            __syncthreads();
        }

        const float* Bw = Bs + (wn * 32) * SMS;

        float c[4][4][4];
#pragma unroll
        for (int i = 0; i < 4; i++)
#pragma unroll
            for (int j = 0; j < 4; j++)
#pragma unroll
                for (int q = 0; q < 4; q++) c[i][j][q] = 0.0f;

        for (int kk = 0; kk < F; kk += 8) {
            uint32_t a[4][4], b[4][2];
#pragma unroll
            for (int i = 0; i < 4; i++) {
                const float* ap = Aw + (i * 16 + gid) * SMS + kk + tig;
                a[i][0] = __float_as_uint(ap[0]);
                a[i][1] = __float_as_uint(ap[8 * SMS]);
                a[i][2] = __float_as_uint(ap[4]);
                a[i][3] = __float_as_uint(ap[8 * SMS + 4]);
            }
#pragma unroll
            for (int j = 0; j < 4; j++) {
                const float* bp = Bw + (j * 8 + gid) * SMS + kk + tig;
                b[j][0] = __float_as_uint(bp[0]);
                b[j][1] = __float_as_uint(bp[4]);
            }
#pragma unroll
            for (int i = 0; i < 4; i++)
#pragma unroll
                for (int j = 0; j < 4; j++)
                    mma_tf32(c[i][j], a[i], b[j]);
        }

        // epilogue
        const float* bias = bt ? bias1 : bias0;
        float* C = bt ? C1 : C0;
#pragma unroll
        for (int i = 0; i < 4; i++) {
            int r0 = row0 + wm * 64 + i * 16 + gid;
            int r1 = r0 + 8;
#pragma unroll
            for (int j = 0; j < 4; j++) {
                int col = wn * 32 + j * 8 + tig * 2;
                float bx = bias[col], by = bias[col + 1];
                float v00 = c[i][j][0] + bx, v01 = c[i][j][1] + by;
                float v10 = c[i][j][2] + bx, v11 = c[i][j][3] + by;
                if (mode == 1) {
                    v00 = fmaxf(v00, 0.f); v01 = fmaxf(v01, 0.f);
                    v10 = fmaxf(v10, 0.f); v11 = fmaxf(v11, 0.f);
                    if (r0 < n) *(__half2*)(H0 + (size_t)r0 * F + col) = __floats2half2_rn(v00, v01);
                    if (r1 < n) *(__half2*)(H0 + (size_t)r1 * F + col) = __floats2half2_rn(v10, v11);
                    continue;
                }
                if (mode == 2) {
                    v00 = 1.f / (1.f + __expf(-v00)); v01 = 1.f / (1.f + __expf(-v01));
                    v10 = 1.f / (1.f + __expf(-v10)); v11 = 1.f / (1.f + __expf(-v11));
                }
                if (r0 < n) *(float2*)(C + (size_t)r0 * F + col) = make_float2(v00, v01);
                if (r1 < n) *(float2*)(C + (size_t)r1 * F + col) = make_float2(v10, v11);

                if (mode == 3 && bt == 1) {
                    if (r0 < n) {
                        float2 mu = *(const float2*)(C0 + (size_t)r0 * F + col);
                        float2 ev = *(const float2*)(eps + (size_t)r0 * F + col);
                        float zx = fmaf(ev.x, __expf(0.5f * v00), mu.x);
                        float zy = fmaf(ev.y, __expf(0.5f * v01), mu.y);
                        *(__half2*)(H0 + (size_t)r0 * F + col) = __floats2half2_rn(zx, zy);
                    }
                    if (r1 < n) {
                        float2 mu = *(const float2*)(C0 + (size_t)r1 * F + col);
                        float2 ev = *(const float2*)(eps + (size_t)r1 * F + col);
                        float zx = fmaf(ev.x, __expf(0.5f * v10), mu.x);
                        float zy = fmaf(ev.y, __expf(0.5f * v11), mu.y);
                        *(__half2*)(H0 + (size_t)r1 * F + col) = __floats2half2_rn(zx, zy);
                    }
                }
            }
        }
    }
}

// ---------------- host ----------------
extern "C" void kernel_launch(void* const* d_in, const int* in_sizes, int n_in,
                              void* d_out, int out_size) {
    const float* x   = (const float*)d_in[0];
    const int*   ei  = (const int*)  d_in[1];
    const float* eps = (const float*)d_in[2];
    const float* W1  = (const float*)d_in[3];
    const float* b1  = (const float*)d_in[4];
    const float* Wmu = (const float*)d_in[5];
    const float* bmu = (const float*)d_in[6];
    const float* Wlv = (const float*)d_in[7];
    const float* blv = (const float*)d_in[8];

    int n = in_sizes[0] / F;
    int e = in_sizes[1] / 2;
    const int* src = ei;
    const int* dst = ei + e;

    float* out   = (float*)d_out;
    float* recon = out;
    float* omu   = out + (size_t)n * F;
    float* olv   = out + 2 * (size_t)n * F;

    void *p0, *ph, *pz, *pw1, *pwmu, *pwlv;
    cudaGetSymbolAddress(&p0, g_buf0);
    cudaGetSymbolAddress(&ph, g_h);
    cudaGetSymbolAddress(&pz, g_z);
    cudaGetSymbolAddress(&pw1, g_wt1);
    cudaGetSymbolAddress(&pwmu, g_wtmu);
    cudaGetSymbolAddress(&pwlv, g_wtlv);
    float*  t0   = (float*)p0;
    __half* h    = (__half*)ph;
    __half* z    = (__half*)pz;
    float*  wt1  = (float*)pw1;
    float*  wtmu = (float*)pwmu;
    float*  wtlv = (float*)pwlv;

    const int TB = 256;
    int gE4 = ((e + 3) / 4 + TB - 1) / TB;
    int gScan = (n + 255) / 256;
    int gGemm = (n + MTILE - 1) / MTILE;
    int gProp = (int)(((size_t)n * 32 + TB - 1) / TB);

    size_t smem = (MTILE + 128) * SMS * sizeof(float);   // A(256) + B(128)
    cudaFuncSetAttribute(k_gemm_mma, cudaFuncAttributeMaxDynamicSharedMemorySize, (int)smem);

    // CSR + dinv + per-edge coefficients (two-phase scan; g_deg pre-zeroed)
    k_count<<<gE4, TB>>>(dst, e);                // 1
    k_scan1<<<gScan, 256>>>(n);                  // 2
    k_scan23<<<gScan, 512>>>(gScan, n);          // 3 (also zeroes g_deg)
    k_place<<<gE4, TB>>>(src, dst, e);           // 4  <- profiled launch

    // encode propagate: t0 = P x   (fp32 table)
    k_prop_f32<<<gProp, TB>>>(x, t0, n);         // 5

    // weights: transpose + tf32 rounding
    k_prep_w<<<dim3(4, 4, 3), dim3(32, 8)>>>(W1, Wmu, Wlv);

    // encode: h = half(relu(t0 W1 + b1))
    k_gemm_mma<<<gGemm, GT, smem>>>(t0, wt1, nullptr, b1, nullptr, nullptr,
                                    nullptr, nullptr, h, n, 1);

    // mu/logvar (+ fused reparameterization, z stored fp16): from P h
    k_prop_f16<<<gProp, TB>>>(h, t0, n);
    k_gemm_mma<<<gGemm, GT, smem>>>(t0, wtmu, wtlv, bmu, blv, eps,
                                    omu, olv, z, n, 3);

    // decode: recon = sigmoid((P z) W1 + b1)
    k_prop_f16<<<gProp, TB>>>(z, t0, n);
    k_gemm_mma<<<gGemm, GT, smem>>>(t0, wt1, nullptr, b1, nullptr, nullptr,
                                    recon, nullptr, nullptr, n, 2);
}

// round 17
// speedup vs baseline: 1.0451x; 1.0451x over previous
#include <cuda_runtime.h>
#include <cuda_fp16.h>
#include <math.h>
#include <stdint.h>

#define F      128
#define NMAX   80000
#define EMAX   640000
#define SMS    132          // smem row stride (floats), conflict-free for frag loads
#define MTILE  256          // GEMM rows per block
#define GT     512          // GEMM threads per block (16 warps)

// ---------------- scratch (static device globals; no allocation) ----------------
// g_deg starts zeroed (static init); k_scan23 re-zeroes it for the next call.
__device__ __align__(16) float  g_buf0[NMAX * F];  // prop output / GEMM input (fp32)
__device__ __align__(16) __half g_h  [NMAX * F];   // hidden after conv1+relu (fp16)
__device__ __align__(16) __half g_z  [NMAX * F];   // latent z (fp16)
__device__ __align__(16) float  g_wt1 [F * F];     // W1^T,  tf32-rounded
__device__ __align__(16) float  g_wtmu[F * F];
__device__ __align__(16) float  g_wtlv[F * F];
__device__ float g_dinv[NMAX];
__device__ float g_coef[EMAX];
__device__ int   g_deg [NMAX];
__device__ int   g_rowptr[NMAX + 1];
__device__ int   g_cur [NMAX];
__device__ int   g_csr [EMAX];
__device__ int   g_bsum[1024];

// ---------------- helpers ----------------
__device__ __forceinline__ float f2tf32(float x) {
    uint32_t b;
    asm("cvt.rna.tf32.f32 %0, %1;" : "=r"(b) : "f"(x));
    return __uint_as_float(b);
}
__device__ __forceinline__ void mma_tf32(float* c, const uint32_t* a, const uint32_t* b) {
    asm volatile(
        "mma.sync.aligned.m16n8k8.row.col.f32.tf32.tf32.f32 "
        "{%0,%1,%2,%3}, {%4,%5,%6,%7}, {%8,%9}, {%0,%1,%2,%3};"
        : "+f"(c[0]), "+f"(c[1]), "+f"(c[2]), "+f"(c[3])
        : "r"(a[0]), "r"(a[1]), "r"(a[2]), "r"(a[3]), "r"(b[0]), "r"(b[1]));
}
__device__ __forceinline__ float4 h4_to_f4(const __half* p) {
    uint2 u = *(const uint2*)p;
    __half2 h0 = *reinterpret_cast<__half2*>(&u.x);
    __half2 h1 = *reinterpret_cast<__half2*>(&u.y);
    float2 f0 = __half22float2(h0), f1 = __half22float2(h1);
    return make_float4(f0.x, f0.y, f1.x, f1.y);
}
// load 8 consecutive halfs (16B) and accumulate: acc[k] += f(h[k]) * c
struct F8 { float4 a, b; };
__device__ __forceinline__ F8 h8_to_f8(const __half* p) {
    uint4 u = *(const uint4*)p;
    __half2 h0 = *reinterpret_cast<__half2*>(&u.x);
    __half2 h1 = *reinterpret_cast<__half2*>(&u.y);
    __half2 h2 = *reinterpret_cast<__half2*>(&u.z);
    __half2 h3 = *reinterpret_cast<__half2*>(&u.w);
    float2 f0 = __half22float2(h0), f1 = __half22float2(h1);
    float2 f2 = __half22float2(h2), f3 = __half22float2(h3);
    F8 r;
    r.a = make_float4(f0.x, f0.y, f1.x, f1.y);
    r.b = make_float4(f2.x, f2.y, f3.x, f3.y);
    return r;
}
__device__ __forceinline__ void fma8(float4& ax, float4& bx, const F8& u, float c) {
    ax.x = fmaf(u.a.x, c, ax.x); ax.y = fmaf(u.a.y, c, ax.y);
    ax.z = fmaf(u.a.z, c, ax.z); ax.w = fmaf(u.a.w, c, ax.w);
    bx.x = fmaf(u.b.x, c, bx.x); bx.y = fmaf(u.b.y, c, bx.y);
    bx.z = fmaf(u.b.z, c, bx.z); bx.w = fmaf(u.b.w, c, bx.w);
}

// ---------------- CSR construction (scalar, R15-proven) ----------------
__global__ void k_count(const int* __restrict__ dst, int e) {
    int i = blockIdx.x * blockDim.x + threadIdx.x;
    if (i < e) atomicAdd(&g_deg[dst[i]], 1);
}
__global__ void k_scan1(int n) {
    __shared__ int s[256];
    int t = threadIdx.x;
    int i = blockIdx.x * 256 + t;
    int d = (i < n) ? g_deg[i] : 0;
    if (i < n) g_dinv[i] = rsqrtf((float)(d + 1));
    s[t] = d; __syncthreads();
#pragma unroll
    for (int off = 1; off < 256; off <<= 1) {
        int v = (t >= off) ? s[t - off] : 0;
        __syncthreads();
        s[t] += v;
        __syncthreads();
    }
    if (i < n) g_rowptr[i] = s[t] - d;
    if (t == 255) g_bsum[blockIdx.x] = s[255];
}
__global__ void k_scan23(int nb, int n) {
    __shared__ int s[512];
    int t = threadIdx.x;
    int v = (t < nb) ? g_bsum[t] : 0;
    s[t] = v; __syncthreads();
#pragma unroll
    for (int off = 1; off < 512; off <<= 1) {
        int u = (t >= off) ? s[t - off] : 0;
        __syncthreads();
        s[t] += u;
        __syncthreads();
    }
    int bid = blockIdx.x;
    if (t < 256) {
        int base = (bid == 0) ? 0 : s[bid - 1];
        int i = bid * 256 + t;
        if (i < n) {
            int r = g_rowptr[i] + base;
            g_rowptr[i] = r;
            g_cur[i] = r;
            g_deg[i] = 0;                // prep for next call
        }
    }
    if (bid == 0 && t == 0) g_rowptr[n] = s[nb - 1];
}
__global__ void k_place(const int* __restrict__ src, const int* __restrict__ dst, int e) {
    int i = blockIdx.x * blockDim.x + threadIdx.x;
    if (i < e) {
        int d = dst[i], s = src[i];
        int slot = atomicAdd(&g_cur[d], 1);
        g_csr[slot] = s;
        g_coef[slot] = g_dinv[s] * g_dinv[d];
    }
}

// ---------------- weight transpose + tf32 rounding ----------------
__global__ void k_prep_w(const float* __restrict__ W1, const float* __restrict__ Wmu,
                         const float* __restrict__ Wlv) {
    const float* src = (blockIdx.z == 0) ? W1 : (blockIdx.z == 1) ? Wmu : Wlv;
    float* dst = (blockIdx.z == 0) ? g_wt1 : (blockIdx.z == 1) ? g_wtmu : g_wtlv;
    __shared__ float t[32][33];
    int tx = threadIdx.x, ty = threadIdx.y;
    int bx = blockIdx.x * 32, by = blockIdx.y * 32;
#pragma unroll
    for (int i = 0; i < 32; i += 8)
        t[ty + i][tx] = src[(by + ty + i) * F + bx + tx];
    __syncthreads();
#pragma unroll
    for (int i = 0; i < 32; i += 8)
        dst[(bx + ty + i) * F + by + tx] = f2tf32(t[tx][ty + i]);
}

// ---------------- propagation (fp32 table): out = P t  (R15-proven) ----------
__global__ __launch_bounds__(256) void k_prop_f32(const float* __restrict__ t,
                                                  float* __restrict__ out, int n) {
    int w = (blockIdx.x * blockDim.x + threadIdx.x) >> 5;
    if (w >= n) return;
    int lane = threadIdx.x & 31;

    const float4* t4 = (const float4*)t;
    float di = g_dinv[w];
    float4 v = t4[(size_t)w * 32 + lane];
    float cs = di * di;
    float4 acc = make_float4(v.x * cs, v.y * cs, v.z * cs, v.w * cs);

    int j = g_rowptr[w], end = g_rowptr[w + 1];
    for (; j + 3 < end; j += 4) {
        int s0 = g_csr[j], s1 = g_csr[j + 1], s2 = g_csr[j + 2], s3 = g_csr[j + 3];
        float c0 = g_coef[j], c1 = g_coef[j + 1], c2 = g_coef[j + 2], c3 = g_coef[j + 3];
        float4 u0 = t4[(size_t)s0 * 32 + lane];
        float4 u1 = t4[(size_t)s1 * 32 + lane];
        float4 u2 = t4[(size_t)s2 * 32 + lane];
        float4 u3 = t4[(size_t)s3 * 32 + lane];
        acc.x = fmaf(u0.x, c0, fmaf(u1.x, c1, fmaf(u2.x, c2, fmaf(u3.x, c3, acc.x))));
        acc.y = fmaf(u0.y, c0, fmaf(u1.y, c1, fmaf(u2.y, c2, fmaf(u3.y, c3, acc.y))));
        acc.z = fmaf(u0.z, c0, fmaf(u1.z, c1, fmaf(u2.z, c2, fmaf(u3.z, c3, acc.z))));
        acc.w = fmaf(u0.w, c0, fmaf(u1.w, c1, fmaf(u2.w, c2, fmaf(u3.w, c3, acc.w))));
    }
    for (; j < end; j++) {
        int s0 = g_csr[j];
        float c0 = g_coef[j];
        float4 u0 = t4[(size_t)s0 * 32 + lane];
        acc.x = fmaf(u0.x, c0, acc.x);
        acc.y = fmaf(u0.y, c0, acc.y);
        acc.z = fmaf(u0.z, c0, acc.z);
        acc.w = fmaf(u0.w, c0, acc.w);
    }
    ((float4*)out)[(size_t)w * 32 + lane] = acc;
}

// ---------------- propagation (fp16 table): half-warp per node ----------------
// 16 lanes x uint4 (8 halves) = one 256B row per half-warp; 2 nodes per warp.
__global__ __launch_bounds__(256) void k_prop_f16(const __half* __restrict__ t,
                                                  float* __restrict__ out, int n) {
    int w = (blockIdx.x * blockDim.x + threadIdx.x) >> 4;   // node per 16 threads
    if (w >= n) return;
    int l = threadIdx.x & 15;
    int fo = l * 8;                                          // this lane's 8 features

    float di = g_dinv[w];
    float cs = di * di;
    F8 v = h8_to_f8(t + (size_t)w * F + fo);
    float4 accA = make_float4(v.a.x * cs, v.a.y * cs, v.a.z * cs, v.a.w * cs);
    float4 accB = make_float4(v.b.x * cs, v.b.y * cs, v.b.z * cs, v.b.w * cs);

    int j = g_rowptr[w], end = g_rowptr[w + 1];
    for (; j + 3 < end; j += 4) {
        int s0 = g_csr[j], s1 = g_csr[j + 1], s2 = g_csr[j + 2], s3 = g_csr[j + 3];
        float c0 = g_coef[j], c1 = g_coef[j + 1], c2 = g_coef[j + 2], c3 = g_coef[j + 3];
        F8 u0 = h8_to_f8(t + (size_t)s0 * F + fo);
        F8 u1 = h8_to_f8(t + (size_t)s1 * F + fo);
        F8 u2 = h8_to_f8(t + (size_t)s2 * F + fo);
        F8 u3 = h8_to_f8(t + (size_t)s3 * F + fo);
        fma8(accA, accB, u0, c0);
        fma8(accA, accB, u1, c1);
        fma8(accA, accB, u2, c2);
        fma8(accA, accB, u3, c3);
    }
    for (; j < end; j++) {
        int s0 = g_csr[j];
        float c0 = g_coef[j];
        F8 u0 = h8_to_f8(t + (size_t)s0 * F + fo);
        fma8(accA, accB, u0, c0);
    }
    float4* o = (float4*)(out + (size_t)w * F + fo);
    o[0] = accA;
    o[1] = accB;
}

// ---------------- TF32 mma.sync GEMM (R15-proven config) ----------------------
// 256-row block tile, 16 warps (512 thr), 64x32 warp tiles -> 4 warps/SMSP.
// mode 1: H0 = half(relu(...))     mode 2: C0 = sigmoid(...)
// mode 3: C0 = mu, C1 = logvar, H0 = half(eps*exp(0.5*lv)+mu)
__global__ __launch_bounds__(GT, 1) void k_gemm_mma(
    const float* __restrict__ A,
    const float* __restrict__ Bt0, const float* __restrict__ Bt1,
    const float* __restrict__ bias0, const float* __restrict__ bias1,
    const float* __restrict__ eps,
    float* __restrict__ C0, float* __restrict__ C1, __half* __restrict__ H0,
    int n, int mode)
{
    extern __shared__ float smf[];
    float* As = smf;                    // MTILE x SMS
    float* Bs = As + MTILE * SMS;       // 128 x SMS

    const int tid  = threadIdx.x;
    const int warp = tid >> 5, lane = tid & 31;
    const int row0 = blockIdx.x * MTILE;
    const int nbt  = (mode == 3) ? 2 : 1;

    // stage A (tf32-round on the fly)
    for (int t = tid; t < MTILE * 32; t += GT) {
        int r = t >> 5, q = t & 31;
        int gr = row0 + r; if (gr >= n) gr = n - 1;
        float4 v = *(const float4*)(A + (size_t)gr * F + q * 4);
        v.x = f2tf32(v.x); v.y = f2tf32(v.y); v.z = f2tf32(v.z); v.w = f2tf32(v.w);
        *(float4*)(As + r * SMS + q * 4) = v;
    }

    const int wm = warp >> 2;    // 0..3  (64-row bands)
    const int wn = warp & 3;     // 0..3  (32-col bands)
    const int gid = lane >> 2, tig = lane & 3;
    const float* Aw = As + (wm * 64) * SMS;

    for (int bt = 0; bt < nbt; bt++) {
        if (bt == 1) __syncthreads();
        {
            const float* Bt = bt ? Bt1 : Bt0;
            for (int q = tid; q < 4096; q += GT) {
                int r = q >> 5, c = q & 31;
                float4 v = *(const float4*)(Bt + (size_t)r * F + c * 4);
                *(float4*)(Bs + r * SMS + c * 4) = v;
            }
        }
        __syncthreads();

        const float* Bw = Bs + (wn * 32) * SMS;

        float c[4][4][4];
#pragma unroll
        for (int i = 0; i < 4; i++)
#pragma unroll
            for (int j = 0; j < 4; j++)
#pragma unroll
                for (int q = 0; q < 4; q++) c[i][j][q] = 0.0f;

        for (int kk = 0; kk < F; kk += 8) {
            uint32_t a[4][4], b[4][2];
#pragma unroll
            for (int i = 0; i < 4; i++) {
                const float* ap = Aw + (i * 16 + gid) * SMS + kk + tig;
                a[i][0] = __float_as_uint(ap[0]);
                a[i][1] = __float_as_uint(ap[8 * SMS]);
                a[i][2] = __float_as_uint(ap[4]);
                a[i][3] = __float_as_uint(ap[8 * SMS + 4]);
            }
#pragma unroll
            for (int j = 0; j < 4; j++) {
                const float* bp = Bw + (j * 8 + gid) * SMS + kk + tig;
                b[j][0] = __float_as_uint(bp[0]);
                b[j][1] = __float_as_uint(bp[4]);
            }
#pragma unroll
            for (int i = 0; i < 4; i++)
#pragma unroll
                for (int j = 0; j < 4; j++)
                    mma_tf32(c[i][j], a[i], b[j]);
        }

        // epilogue
        const float* bias = bt ? bias1 : bias0;
        float* C = bt ? C1 : C0;
#pragma unroll
        for (int i = 0; i < 4; i++) {
            int r0 = row0 + wm * 64 + i * 16 + gid;
            int r1 = r0 + 8;
#pragma unroll
            for (int j = 0; j < 4; j++) {
                int col = wn * 32 + j * 8 + tig * 2;
                float bx = bias[col], by = bias[col + 1];
                float v00 = c[i][j][0] + bx, v01 = c[i][j][1] + by;
                float v10 = c[i][j][2] + bx, v11 = c[i][j][3] + by;
                if (mode == 1) {
                    v00 = fmaxf(v00, 0.f); v01 = fmaxf(v01, 0.f);
                    v10 = fmaxf(v10, 0.f); v11 = fmaxf(v11, 0.f);
                    if (r0 < n) *(__half2*)(H0 + (size_t)r0 * F + col) = __floats2half2_rn(v00, v01);
                    if (r1 < n) *(__half2*)(H0 + (size_t)r1 * F + col) = __floats2half2_rn(v10, v11);
                    continue;
                }
                if (mode == 2) {
                    v00 = 1.f / (1.f + __expf(-v00)); v01 = 1.f / (1.f + __expf(-v01));
                    v10 = 1.f / (1.f + __expf(-v10)); v11 = 1.f / (1.f + __expf(-v11));
                }
                if (r0 < n) *(float2*)(C + (size_t)r0 * F + col) = make_float2(v00, v01);
                if (r1 < n) *(float2*)(C + (size_t)r1 * F + col) = make_float2(v10, v11);

                if (mode == 3 && bt == 1) {
                    if (r0 < n) {
                        float2 mu = *(const float2*)(C0 + (size_t)r0 * F + col);
                        float2 ev = *(const float2*)(eps + (size_t)r0 * F + col);
                        float zx = fmaf(ev.x, __expf(0.5f * v00), mu.x);
                        float zy = fmaf(ev.y, __expf(0.5f * v01), mu.y);
                        *(__half2*)(H0 + (size_t)r0 * F + col) = __floats2half2_rn(zx, zy);
                    }
                    if (r1 < n) {
                        float2 mu = *(const float2*)(C0 + (size_t)r1 * F + col);
                        float2 ev = *(const float2*)(eps + (size_t)r1 * F + col);
                        float zx = fmaf(ev.x, __expf(0.5f * v10), mu.x);
                        float zy = fmaf(ev.y, __expf(0.5f * v11), mu.y);
                        *(__half2*)(H0 + (size_t)r1 * F + col) = __floats2half2_rn(zx, zy);
                    }
                }
            }
        }
    }
}

// ---------------- host ----------------
extern "C" void kernel_launch(void* const* d_in, const int* in_sizes, int n_in,
                              void* d_out, int out_size) {
    const float* x   = (const float*)d_in[0];
    const int*   ei  = (const int*)  d_in[1];
    const float* eps = (const float*)d_in[2];
    const float* W1  = (const float*)d_in[3];
    const float* b1  = (const float*)d_in[4];
    const float* Wmu = (const float*)d_in[5];
    const float* bmu = (const float*)d_in[6];
    const float* Wlv = (const float*)d_in[7];
    const float* blv = (const float*)d_in[8];

    int n = in_sizes[0] / F;
    int e = in_sizes[1] / 2;
    const int* src = ei;
    const int* dst = ei + e;

    float* out   = (float*)d_out;
    float* recon = out;
    float* omu   = out + (size_t)n * F;
    float* olv   = out + 2 * (size_t)n * F;

    void *p0, *ph, *pz, *pw1, *pwmu, *pwlv;
    cudaGetSymbolAddress(&p0, g_buf0);
    cudaGetSymbolAddress(&ph, g_h);
    cudaGetSymbolAddress(&pz, g_z);
    cudaGetSymbolAddress(&pw1, g_wt1);
    cudaGetSymbolAddress(&pwmu, g_wtmu);
    cudaGetSymbolAddress(&pwlv, g_wtlv);
    float*  t0   = (float*)p0;
    __half* h    = (__half*)ph;
    __half* z    = (__half*)pz;
    float*  wt1  = (float*)pw1;
    float*  wtmu = (float*)pwmu;
    float*  wtlv = (float*)pwlv;

    const int TB = 256;
    int gE = (e + TB - 1) / TB;
    int gScan = (n + 255) / 256;
    int gGemm = (n + MTILE - 1) / MTILE;
    int gProp32 = (int)(((size_t)n * 32 + TB - 1) / TB);
    int gProp16 = (int)(((size_t)n * 16 + TB - 1) / TB);

    size_t smem = (MTILE + 128) * SMS * sizeof(float);   // A(256) + B(128)
    cudaFuncSetAttribute(k_gemm_mma, cudaFuncAttributeMaxDynamicSharedMemorySize, (int)smem);

    // CSR + dinv + per-edge coefficients (two-phase scan; g_deg pre-zeroed)
    k_count<<<gE, TB>>>(dst, e);                 // 1
    k_scan1<<<gScan, 256>>>(n);                  // 2
    k_scan23<<<gScan, 512>>>(gScan, n);          // 3 (also zeroes g_deg)
    k_place<<<gE, TB>>>(src, dst, e);            // 4

    // encode propagate: t0 = P x   (fp32 table)
    k_prop_f32<<<gProp32, TB>>>(x, t0, n);       // 5

    // weights: transpose + tf32 rounding
    k_prep_w<<<dim3(4, 4, 3), dim3(32, 8)>>>(W1, Wmu, Wlv);

    // encode: h = half(relu(t0 W1 + b1))
    k_gemm_mma<<<gGemm, GT, smem>>>(t0, wt1, nullptr, b1, nullptr, nullptr,
                                    nullptr, nullptr, h, n, 1);

    // mu/logvar (+ fused reparameterization, z stored fp16): from P h
    k_prop_f16<<<gProp16, TB>>>(h, t0, n);
    k_gemm_mma<<<gGemm, GT, smem>>>(t0, wtmu, wtlv, bmu, blv, eps,
                                    omu, olv, z, n, 3);

    // decode: recon = sigmoid((P z) W1 + b1)
    k_prop_f16<<<gProp16, TB>>>(z, t0, n);
    k_gemm_mma<<<gGemm, GT, smem>>>(t0, wt1, nullptr, b1, nullptr, nullptr,
                                    recon, nullptr, nullptr, n, 2);
}